// round 5
// baseline (speedup 1.0000x reference)
#include <cuda_runtime.h>
#include <cuda_bf16.h>
#include <math.h>
#include <stdint.h>

namespace {

constexpr int T_TOK = 8192;
constexpr int DIM   = 512;
constexpr int FDIM  = 2048;
constexpr int NEXP  = 8;
constexpr int MAXB  = 8192;
constexpr int NROWS = 2 * T_TOK;

// GEMM tiling: CTA 128x128, K-slab 32 (bf16), 8 warps as 2(M) x 4(N), warp tile 64x32
constexpr int BM = 128, BN = 128, BK = 32;
constexpr int AST = 40;    // A smem row stride (bf16): conflict-free for ldmatrix (20w)
constexpr int BST = 136;   // B smem row stride (bf16): 68w, 4r mod 32 distinct
constexpr int A_PLANE = BM * AST * 2;            // 10240 B
constexpr int B_PLANE = BK * BST * 2;            // 8704 B
constexpr int STAGE   = 2 * A_PLANE + 2 * B_PLANE;  // 37888 B
constexpr int SMEM_BYTES = 2 * STAGE;            // 75776 B

// ---- device scratch ----
__device__ int   g_count[NEXP];
__device__ int   g_offset[NEXP];
__device__ float g_probsum[NEXP];
__device__ int   g_tok[NEXP * MAXB];
__device__ int   g_slot[T_TOK * 2];
__device__ float g_slotw[T_TOK * 2];
__device__ __nv_bfloat16 g_xh[(size_t)T_TOK * DIM];
__device__ __nv_bfloat16 g_xl[(size_t)T_TOK * DIM];
__device__ __nv_bfloat16 g_w1h[(size_t)NEXP * DIM * FDIM];   // natural [E][D][F] = [E][K][N]
__device__ __nv_bfloat16 g_w1l[(size_t)NEXP * DIM * FDIM];
__device__ __nv_bfloat16 g_w2h[(size_t)NEXP * FDIM * DIM];   // natural [E][F][D] = [E][K][N]
__device__ __nv_bfloat16 g_w2l[(size_t)NEXP * FDIM * DIM];
__device__ __nv_bfloat16 g_hh[(size_t)NROWS * FDIM];
__device__ __nv_bfloat16 g_hl[(size_t)NROWS * FDIM];
__device__ float g_oscr[(size_t)NROWS * DIM];

// ---- PTX helpers ----
__device__ __forceinline__ uint32_t smem_u32(const void* p) {
    uint32_t a;
    asm("{ .reg .u64 t; cvta.to.shared.u64 t, %1; cvt.u32.u64 %0, t; }" : "=r"(a) : "l"(p));
    return a;
}
__device__ __forceinline__ void cp_async16(uint32_t saddr, const void* g) {
    asm volatile("cp.async.cg.shared.global [%0], [%1], 16;" :: "r"(saddr), "l"(g));
}
__device__ __forceinline__ void cp_commit() { asm volatile("cp.async.commit_group;" ::: "memory"); }
__device__ __forceinline__ void cp_wait1()  { asm volatile("cp.async.wait_group 1;" ::: "memory"); }
__device__ __forceinline__ void cp_wait0()  { asm volatile("cp.async.wait_group 0;" ::: "memory"); }

__device__ __forceinline__ void ldsm4(uint32_t& r0, uint32_t& r1, uint32_t& r2, uint32_t& r3,
                                      uint32_t a) {
    asm volatile("ldmatrix.sync.aligned.m8n8.x4.shared.b16 {%0,%1,%2,%3}, [%4];"
                 : "=r"(r0), "=r"(r1), "=r"(r2), "=r"(r3) : "r"(a));
}
__device__ __forceinline__ void ldsm4t(uint32_t& r0, uint32_t& r1, uint32_t& r2, uint32_t& r3,
                                       uint32_t a) {
    asm volatile("ldmatrix.sync.aligned.m8n8.x4.trans.shared.b16 {%0,%1,%2,%3}, [%4];"
                 : "=r"(r0), "=r"(r1), "=r"(r2), "=r"(r3) : "r"(a));
}
__device__ __forceinline__ void mma_bf16(float c[4], const uint32_t a[4],
                                         uint32_t b0, uint32_t b1) {
    asm volatile(
        "mma.sync.aligned.m16n8k16.row.col.f32.bf16.bf16.f32 "
        "{%0,%1,%2,%3}, {%4,%5,%6,%7}, {%8,%9}, {%0,%1,%2,%3};"
        : "+f"(c[0]), "+f"(c[1]), "+f"(c[2]), "+f"(c[3])
        : "r"(a[0]), "r"(a[1]), "r"(a[2]), "r"(a[3]), "r"(b0), "r"(b1));
}

// ---- small kernels ----
__global__ void init_k() {
    if (threadIdx.x < NEXP) { g_count[threadIdx.x] = 0; g_probsum[threadIdx.x] = 0.f; }
}

__global__ void router_k(const float* __restrict__ x, const float* __restrict__ gw) {
    __shared__ float s_gw[DIM * NEXP];
    for (int i = threadIdx.x; i < DIM * NEXP; i += blockDim.x) s_gw[i] = gw[i];
    __syncthreads();

    int t    = (int)((blockIdx.x * blockDim.x + threadIdx.x) >> 5);
    int lane = threadIdx.x & 31;
    if (t >= T_TOK) return;

    const float* xr = x + (size_t)t * DIM;
    float acc[NEXP];
#pragma unroll
    for (int e = 0; e < NEXP; e++) acc[e] = 0.f;
    for (int d = lane; d < DIM; d += 32) {
        float xv = xr[d];
#pragma unroll
        for (int e = 0; e < NEXP; e++) acc[e] = fmaf(xv, s_gw[d * NEXP + e], acc[e]);
    }
#pragma unroll
    for (int off = 16; off; off >>= 1) {
#pragma unroll
        for (int e = 0; e < NEXP; e++)
            acc[e] += __shfl_xor_sync(0xffffffffu, acc[e], off);
    }
    if (lane != 0) return;

    float mx = acc[0];
#pragma unroll
    for (int e = 1; e < NEXP; e++) mx = fmaxf(mx, acc[e]);
    float p[NEXP]; float s = 0.f;
#pragma unroll
    for (int e = 0; e < NEXP; e++) { p[e] = expf(acc[e] - mx); s += p[e]; }
    float inv = 1.f / s;
#pragma unroll
    for (int e = 0; e < NEXP; e++) { p[e] *= inv; atomicAdd(&g_probsum[e], p[e]); }

    int i0 = 0;
#pragma unroll
    for (int e = 1; e < NEXP; e++) if (p[e] > p[i0]) i0 = e;
    int i1 = (i0 == 0) ? 1 : 0;
#pragma unroll
    for (int e = 0; e < NEXP; e++) if (e != i0 && p[e] > p[i1]) i1 = e;

    float w0 = p[i0], w1 = p[i1];
    float ws = 1.f / (w0 + w1);
    w0 *= ws; w1 *= ws;

    int p0 = atomicAdd(&g_count[i0], 1);
    g_tok[i0 * MAXB + p0] = t;
    g_slot[t * 2 + 0]  = i0 * MAXB + p0;
    g_slotw[t * 2 + 0] = w0;
    int p1 = atomicAdd(&g_count[i1], 1);
    g_tok[i1 * MAXB + p1] = t;
    g_slot[t * 2 + 1]  = i1 * MAXB + p1;
    g_slotw[t * 2 + 1] = w1;
}

__global__ void finalize_k(float* __restrict__ loss_out) {
    int off = 0;
    for (int e = 0; e < NEXP; e++) { g_offset[e] = off; off += g_count[e]; }
    float s = 0.f;
    for (int e = 0; e < NEXP; e++) {
        float m = g_probsum[e] * (1.f / (float)T_TOK);
        s += m * m;
    }
    *loss_out = (float)NEXP * s;
}

// fp32 -> (hi, lo) bf16 planes, elementwise (float4)
__global__ void split_k(const float* __restrict__ s, __nv_bfloat16* __restrict__ h,
                        __nv_bfloat16* __restrict__ l, int n4) {
    int i = blockIdx.x * blockDim.x + threadIdx.x;
    if (i >= n4) return;
    float4 v = ((const float4*)s)[i];
    __nv_bfloat16 h0 = __float2bfloat16_rn(v.x), h1 = __float2bfloat16_rn(v.y);
    __nv_bfloat16 h2 = __float2bfloat16_rn(v.z), h3 = __float2bfloat16_rn(v.w);
    __nv_bfloat16 l0 = __float2bfloat16_rn(v.x - __bfloat162float(h0));
    __nv_bfloat16 l1 = __float2bfloat16_rn(v.y - __bfloat162float(h1));
    __nv_bfloat16 l2 = __float2bfloat16_rn(v.z - __bfloat162float(h2));
    __nv_bfloat16 l3 = __float2bfloat16_rn(v.w - __bfloat162float(h3));
    ((__nv_bfloat162*)h)[2 * i]     = __halves2bfloat162(h0, h1);
    ((__nv_bfloat162*)h)[2 * i + 1] = __halves2bfloat162(h2, h3);
    ((__nv_bfloat162*)l)[2 * i]     = __halves2bfloat162(l0, l1);
    ((__nv_bfloat162*)l)[2 * i + 1] = __halves2bfloat162(l2, l3);
}

// ---- bf16x2 hi/lo tensor-core FFN GEMM ----
// D[128,128] = (Ah+Al)[gathered rows, K] @ (Bh+Bl)[K, N] using 3-term split.
template <int KFULL, int NFULL, bool GELU, bool GATHER>
__global__ __launch_bounds__(256, 2) void ffn_k(
    const __nv_bfloat16* __restrict__ Ah, const __nv_bfloat16* __restrict__ Al,
    const __nv_bfloat16* __restrict__ Bh, const __nv_bfloat16* __restrict__ Bl,
    const float* __restrict__ bias,
    __nv_bfloat16* __restrict__ OutH, __nv_bfloat16* __restrict__ OutL,
    float* __restrict__ OutF) {
    const int e  = blockIdx.z;
    const int ne = g_count[e];
    const int m0 = blockIdx.y * BM;
    if (m0 >= ne) return;
    const int n0   = blockIdx.x * BN;
    const int base = g_offset[e];

    extern __shared__ __align__(16) char smem[];
    const uint32_t sb = smem_u32(smem);
    const int tid  = threadIdx.x;
    const int lane = tid & 31;
    const int warp = tid >> 5;
    const int wm   = (warp & 1) * 64;
    const int wn   = (warp >> 1) * 32;

    // ---- cp.async addressing (8 x 16B chunks per thread per stage) ----
    const __nv_bfloat16* sA[4];
    uint32_t dA[4];
#pragma unroll
    for (int l = 0; l < 4; l++) {
        int idx = tid + l * 256;          // 0..1023
        int plane = idx >> 9;             // 0 = hi, 1 = lo
        int row = (idx & 511) >> 2;       // 0..127
        int ch  = idx & 3;                // 16B chunk within 64B row slab
        int r;
        if (GATHER) r = g_tok[e * MAXB + min(m0 + row, ne - 1)];
        else        r = base + min(m0 + row, ne - 1);
        sA[l] = (plane ? Al : Ah) + (size_t)r * KFULL + ch * 8;
        dA[l] = (uint32_t)(plane * A_PLANE + row * (AST * 2) + ch * 16);
    }
    const __nv_bfloat16* sB[4];
    uint32_t dB[4];
#pragma unroll
    for (int l = 0; l < 4; l++) {
        int idx = tid + l * 256;
        int plane = idx >> 9;
        int k  = (idx & 511) >> 4;        // 0..31
        int ch = idx & 15;                // 16 chunks of 8 bf16 across N=128
        const __nv_bfloat16* Bp = (plane ? Bl : Bh) + (size_t)e * KFULL * NFULL;
        sB[l] = Bp + (size_t)k * NFULL + n0 + ch * 8;
        dB[l] = (uint32_t)(2 * A_PLANE + plane * B_PLANE + k * (BST * 2) + ch * 16);
    }

    auto load_stage = [&](int s, int k0) {
        uint32_t st = sb + (uint32_t)(s * STAGE);
#pragma unroll
        for (int l = 0; l < 4; l++) cp_async16(st + dA[l], sA[l] + k0);
#pragma unroll
        for (int l = 0; l < 4; l++) cp_async16(st + dB[l], sB[l] + (size_t)k0 * NFULL);
    };

    // ---- ldmatrix lane addressing ----
    const int lm = lane >> 3;                      // matrix index 0..3
    const int aR = (lm & 1) * 8 + (lane & 7);      // row within 16-row tile
    const int aK = (lm >> 1) * 8;                  // k-half
    const int bK = (lm & 1) * 8 + (lane & 7);      // k row (B, trans)
    const int bN = (lm >> 1) * 8;                  // n-half

    float acc[4][4][4];
#pragma unroll
    for (int i = 0; i < 4; i++)
#pragma unroll
        for (int j = 0; j < 4; j++)
#pragma unroll
            for (int k = 0; k < 4; k++) acc[i][j][k] = 0.f;

    constexpr int KITERS = KFULL / BK;
    load_stage(0, 0);
    cp_commit();

    for (int it = 0; it < KITERS; it++) {
        if (it + 1 < KITERS) {
            load_stage((it + 1) & 1, (it + 1) * BK);
            cp_commit();
            cp_wait1();
        } else {
            cp_wait0();
        }
        __syncthreads();
        uint32_t st = sb + (uint32_t)((it & 1) * STAGE);
#pragma unroll
        for (int ks = 0; ks < 2; ks++) {
            const int k0s = ks * 16;
            uint32_t ah[4][4], al[4][4];
#pragma unroll
            for (int mt = 0; mt < 4; mt++) {
                uint32_t a0 = st + (uint32_t)(((wm + mt * 16 + aR) * AST + k0s + aK) * 2);
                ldsm4(ah[mt][0], ah[mt][1], ah[mt][2], ah[mt][3], a0);
                ldsm4(al[mt][0], al[mt][1], al[mt][2], al[mt][3], a0 + A_PLANE);
            }
#pragma unroll
            for (int pair = 0; pair < 2; pair++) {
                uint32_t b0 = st + 2 * A_PLANE +
                              (uint32_t)(((k0s + bK) * BST + wn + pair * 16 + bN) * 2);
                uint32_t bh[4], bl[4];
                ldsm4t(bh[0], bh[1], bh[2], bh[3], b0);
                ldsm4t(bl[0], bl[1], bl[2], bl[3], b0 + B_PLANE);
#pragma unroll
                for (int j = 0; j < 2; j++) {
                    const int nt = pair * 2 + j;
#pragma unroll
                    for (int mt = 0; mt < 4; mt++) {
                        mma_bf16(acc[mt][nt], ah[mt], bh[2 * j], bh[2 * j + 1]);
                        mma_bf16(acc[mt][nt], ah[mt], bl[2 * j], bl[2 * j + 1]);
                        mma_bf16(acc[mt][nt], al[mt], bh[2 * j], bh[2 * j + 1]);
                    }
                }
            }
        }
        __syncthreads();
    }

    // ---- epilogue ----
#pragma unroll
    for (int nt = 0; nt < 4; nt++) {
        int c = n0 + wn + nt * 8 + 2 * (lane & 3);
        float2 bb = *(const float2*)(bias + (size_t)e * NFULL + c);
#pragma unroll
        for (int mt = 0; mt < 4; mt++) {
            int r = wm + mt * 16 + (lane >> 2);
            int mrow0 = m0 + r, mrow1 = mrow0 + 8;
            if (GELU) {
                if (mrow0 < ne) {
                    float v0 = acc[mt][nt][0] + bb.x;
                    float v1 = acc[mt][nt][1] + bb.y;
                    v0 = v0 * normcdff(v0);
                    v1 = v1 * normcdff(v1);
                    __nv_bfloat16 h0 = __float2bfloat16_rn(v0), h1 = __float2bfloat16_rn(v1);
                    __nv_bfloat16 l0 = __float2bfloat16_rn(v0 - __bfloat162float(h0));
                    __nv_bfloat16 l1 = __float2bfloat16_rn(v1 - __bfloat162float(h1));
                    size_t o = (size_t)(base + mrow0) * NFULL + c;
                    *(__nv_bfloat162*)(OutH + o) = __halves2bfloat162(h0, h1);
                    *(__nv_bfloat162*)(OutL + o) = __halves2bfloat162(l0, l1);
                }
                if (mrow1 < ne) {
                    float v2 = acc[mt][nt][2] + bb.x;
                    float v3 = acc[mt][nt][3] + bb.y;
                    v2 = v2 * normcdff(v2);
                    v3 = v3 * normcdff(v3);
                    __nv_bfloat16 h2 = __float2bfloat16_rn(v2), h3 = __float2bfloat16_rn(v3);
                    __nv_bfloat16 l2 = __float2bfloat16_rn(v2 - __bfloat162float(h2));
                    __nv_bfloat16 l3 = __float2bfloat16_rn(v3 - __bfloat162float(h3));
                    size_t o = (size_t)(base + mrow1) * NFULL + c;
                    *(__nv_bfloat162*)(OutH + o) = __halves2bfloat162(h2, h3);
                    *(__nv_bfloat162*)(OutL + o) = __halves2bfloat162(l2, l3);
                }
            } else {
                if (mrow0 < ne) {
                    float2 o = { acc[mt][nt][0] + bb.x, acc[mt][nt][1] + bb.y };
                    *(float2*)(OutF + (size_t)(base + mrow0) * NFULL + c) = o;
                }
                if (mrow1 < ne) {
                    float2 o = { acc[mt][nt][2] + bb.x, acc[mt][nt][3] + bb.y };
                    *(float2*)(OutF + (size_t)(base + mrow1) * NFULL + c) = o;
                }
            }
        }
    }
}

__global__ void combine_k(float* __restrict__ y) {
    int gid = blockIdx.x * blockDim.x + threadIdx.x;
    if (gid >= T_TOK * (DIM / 4)) return;
    int t = gid >> 7;
    int q = (gid & 127) * 4;
    int s0 = g_slot[t * 2 + 0], s1 = g_slot[t * 2 + 1];
    float w0 = g_slotw[t * 2 + 0], w1 = g_slotw[t * 2 + 1];
    int r0 = g_offset[s0 >> 13] + (s0 & (MAXB - 1));
    int r1 = g_offset[s1 >> 13] + (s1 & (MAXB - 1));
    float4 a = *(const float4*)(g_oscr + (size_t)r0 * DIM + q);
    float4 b = *(const float4*)(g_oscr + (size_t)r1 * DIM + q);
    float4 o;
    o.x = w0 * a.x + w1 * b.x;
    o.y = w0 * a.y + w1 * b.y;
    o.z = w0 * a.z + w1 * b.z;
    o.w = w0 * a.w + w1 * b.w;
    *(float4*)(y + (size_t)t * DIM + q) = o;
}

}  // namespace

extern "C" void kernel_launch(void* const* d_in, const int* in_sizes, int n_in,
                              void* d_out, int out_size) {
    const float* x  = (const float*)d_in[0];
    const float* gw = (const float*)d_in[1];
    const float* w1 = (const float*)d_in[2];
    const float* b1 = (const float*)d_in[3];
    const float* w2 = (const float*)d_in[4];
    const float* b2 = (const float*)d_in[5];
    float* y    = (float*)d_out;
    float* loss = y + (out_size - 1);

    static bool attr_done = false;
    if (!attr_done) {
        cudaFuncSetAttribute((const void*)ffn_k<DIM, FDIM, true, true>,
                             cudaFuncAttributeMaxDynamicSharedMemorySize, SMEM_BYTES);
        cudaFuncSetAttribute((const void*)ffn_k<FDIM, DIM, false, false>,
                             cudaFuncAttributeMaxDynamicSharedMemorySize, SMEM_BYTES);
        attr_done = true;
    }

    __nv_bfloat16 *xh, *xl, *w1h, *w1l, *w2h, *w2l, *hh, *hl;
    float* oscr;
    cudaGetSymbolAddress((void**)&xh,  g_xh);
    cudaGetSymbolAddress((void**)&xl,  g_xl);
    cudaGetSymbolAddress((void**)&w1h, g_w1h);
    cudaGetSymbolAddress((void**)&w1l, g_w1l);
    cudaGetSymbolAddress((void**)&w2h, g_w2h);
    cudaGetSymbolAddress((void**)&w2l, g_w2l);
    cudaGetSymbolAddress((void**)&hh,  g_hh);
    cudaGetSymbolAddress((void**)&hl,  g_hl);
    cudaGetSymbolAddress((void**)&oscr, g_oscr);

    init_k<<<1, 32>>>();
    router_k<<<(T_TOK * 32 + 255) / 256, 256>>>(x, gw);
    finalize_k<<<1, 1>>>(loss);

    constexpr int XN4  = T_TOK * DIM / 4;
    constexpr int W1N4 = NEXP * DIM * FDIM / 4;
    constexpr int W2N4 = NEXP * FDIM * DIM / 4;
    split_k<<<(XN4 + 255) / 256, 256>>>(x, xh, xl, XN4);
    split_k<<<(W1N4 + 255) / 256, 256>>>(w1, w1h, w1l, W1N4);
    split_k<<<(W2N4 + 255) / 256, 256>>>(w2, w2h, w2l, W2N4);

    ffn_k<DIM, FDIM, true, true>
        <<<dim3(FDIM / BN, MAXB / BM, NEXP), 256, SMEM_BYTES>>>(
            xh, xl, w1h, w1l, b1, hh, hl, nullptr);

    ffn_k<FDIM, DIM, false, false>
        <<<dim3(DIM / BN, MAXB / BM, NEXP), 256, SMEM_BYTES>>>(
            hh, hl, w2h, w2l, b2, nullptr, nullptr, oscr);

    combine_k<<<(T_TOK * (DIM / 4) + 255) / 256, 256>>>(y);
}

// round 6
// speedup vs baseline: 1.0689x; 1.0689x over previous
#include <cuda_runtime.h>
#include <math.h>
#include <stdint.h>

namespace {

constexpr int T_TOK = 8192;
constexpr int DIM   = 512;
constexpr int FDIM  = 2048;
constexpr int NEXP  = 8;
constexpr int MAXB  = 8192;
constexpr int NROWS = 2 * T_TOK;

// CTA 128x128, 4 warps (2x2), warp tile 64x64, BK=32 (tf32), 3-stage cp.async
constexpr int BM = 128, BN = 128, BK = 32;
constexpr int SROW = 36;                         // smem row stride in words (conflict-free)
constexpr int A_WORDS = BM * SROW;               // 4608
constexpr int B_WORDS = BN * SROW;               // 4608
constexpr int A_BYTES = A_WORDS * 4;             // 18432
constexpr int STAGE_BYTES = (A_WORDS + B_WORDS) * 4;  // 36864
constexpr int NSTAGE = 3;
constexpr int SMEM_BYTES = NSTAGE * STAGE_BYTES; // 110592

// ---- device scratch ----
__device__ int   g_count[NEXP];
__device__ int   g_offset[NEXP];
__device__ float g_probsum[NEXP];
__device__ int   g_tok[NEXP * MAXB];
__device__ int   g_slot[T_TOK * 2];
__device__ float g_slotw[T_TOK * 2];
__device__ float g_xr[(size_t)T_TOK * DIM];            // tf32-rounded x
__device__ float g_w1t[(size_t)NEXP * FDIM * DIM];     // w1^T rounded [E][F][D]
__device__ float g_w2t[(size_t)NEXP * DIM * FDIM];     // w2^T rounded [E][D][F]
__device__ float g_hidden[(size_t)NROWS * FDIM];       // tf32-rounded
__device__ float g_oscr[(size_t)NROWS * DIM];

// ---- PTX helpers ----
__device__ __forceinline__ uint32_t smem_u32(const void* p) {
    uint32_t a;
    asm("{ .reg .u64 t; cvta.to.shared.u64 t, %1; cvt.u32.u64 %0, t; }" : "=r"(a) : "l"(p));
    return a;
}
__device__ __forceinline__ void cp_async16(uint32_t saddr, const void* g) {
    asm volatile("cp.async.cg.shared.global [%0], [%1], 16;" :: "r"(saddr), "l"(g));
}
__device__ __forceinline__ void cp_commit() { asm volatile("cp.async.commit_group;" ::: "memory"); }
__device__ __forceinline__ void cp_wait1()  { asm volatile("cp.async.wait_group 1;" ::: "memory"); }
__device__ __forceinline__ void cp_wait0()  { asm volatile("cp.async.wait_group 0;" ::: "memory"); }
__device__ __forceinline__ uint32_t f2tf32(float f) {
    uint32_t r;
    asm("cvt.rna.tf32.f32 %0, %1;" : "=r"(r) : "f"(f));
    return r;
}
__device__ __forceinline__ void ldsm4(uint32_t& r0, uint32_t& r1, uint32_t& r2, uint32_t& r3,
                                      uint32_t a) {
    asm volatile("ldmatrix.sync.aligned.m8n8.x4.shared.b16 {%0,%1,%2,%3}, [%4];"
                 : "=r"(r0), "=r"(r1), "=r"(r2), "=r"(r3) : "r"(a));
}
__device__ __forceinline__ void mma_tf32(float c[4], uint32_t a0, uint32_t a1,
                                         uint32_t a2, uint32_t a3,
                                         uint32_t b0, uint32_t b1) {
    asm volatile(
        "mma.sync.aligned.m16n8k8.row.col.f32.tf32.tf32.f32 "
        "{%0,%1,%2,%3}, {%4,%5,%6,%7}, {%8,%9}, {%0,%1,%2,%3};"
        : "+f"(c[0]), "+f"(c[1]), "+f"(c[2]), "+f"(c[3])
        : "r"(a0), "r"(a1), "r"(a2), "r"(a3), "r"(b0), "r"(b1));
}

// ---- small kernels ----
__global__ void init_k() {
    if (threadIdx.x < NEXP) { g_count[threadIdx.x] = 0; g_probsum[threadIdx.x] = 0.f; }
}

__global__ void router_k(const float* __restrict__ x, const float* __restrict__ gw) {
    __shared__ float s_gw[DIM * NEXP];
    for (int i = threadIdx.x; i < DIM * NEXP; i += blockDim.x) s_gw[i] = gw[i];
    __syncthreads();

    int t    = (int)((blockIdx.x * blockDim.x + threadIdx.x) >> 5);
    int lane = threadIdx.x & 31;
    if (t >= T_TOK) return;

    const float* xr = x + (size_t)t * DIM;
    float acc[NEXP];
#pragma unroll
    for (int e = 0; e < NEXP; e++) acc[e] = 0.f;
    for (int d = lane; d < DIM; d += 32) {
        float xv = xr[d];
#pragma unroll
        for (int e = 0; e < NEXP; e++) acc[e] = fmaf(xv, s_gw[d * NEXP + e], acc[e]);
    }
#pragma unroll
    for (int off = 16; off; off >>= 1) {
#pragma unroll
        for (int e = 0; e < NEXP; e++)
            acc[e] += __shfl_xor_sync(0xffffffffu, acc[e], off);
    }
    if (lane != 0) return;

    float mx = acc[0];
#pragma unroll
    for (int e = 1; e < NEXP; e++) mx = fmaxf(mx, acc[e]);
    float p[NEXP]; float s = 0.f;
#pragma unroll
    for (int e = 0; e < NEXP; e++) { p[e] = expf(acc[e] - mx); s += p[e]; }
    float inv = 1.f / s;
#pragma unroll
    for (int e = 0; e < NEXP; e++) { p[e] *= inv; atomicAdd(&g_probsum[e], p[e]); }

    int i0 = 0;
#pragma unroll
    for (int e = 1; e < NEXP; e++) if (p[e] > p[i0]) i0 = e;
    int i1 = (i0 == 0) ? 1 : 0;
#pragma unroll
    for (int e = 0; e < NEXP; e++) if (e != i0 && p[e] > p[i1]) i1 = e;

    float w0 = p[i0], w1 = p[i1];
    float ws = 1.f / (w0 + w1);
    w0 *= ws; w1 *= ws;

    int p0 = atomicAdd(&g_count[i0], 1);
    g_tok[i0 * MAXB + p0] = t;
    g_slot[t * 2 + 0]  = i0 * MAXB + p0;
    g_slotw[t * 2 + 0] = w0;
    int p1 = atomicAdd(&g_count[i1], 1);
    g_tok[i1 * MAXB + p1] = t;
    g_slot[t * 2 + 1]  = i1 * MAXB + p1;
    g_slotw[t * 2 + 1] = w1;
}

__global__ void finalize_k(float* __restrict__ loss_out) {
    int off = 0;
    for (int e = 0; e < NEXP; e++) { g_offset[e] = off; off += g_count[e]; }
    float s = 0.f;
    for (int e = 0; e < NEXP; e++) {
        float m = g_probsum[e] * (1.f / (float)T_TOK);
        s += m * m;
    }
    *loss_out = (float)NEXP * s;
}

// elementwise tf32 pre-round
__global__ void round_k(const float* __restrict__ src, float* __restrict__ dst, int n4) {
    int i = blockIdx.x * blockDim.x + threadIdx.x;
    if (i >= n4) return;
    float4 v = ((const float4*)src)[i];
    uint4 o;
    o.x = f2tf32(v.x); o.y = f2tf32(v.y); o.z = f2tf32(v.z); o.w = f2tf32(v.w);
    ((uint4*)dst)[i] = o;
}

// src [E][R][C] -> dst [E][C][R], tf32-rounded
__global__ void transpose_round_k(const float* __restrict__ src, float* __restrict__ dst,
                                  int R, int C) {
    __shared__ float tile[32][33];
    int e = blockIdx.z;
    const float* s = src + (size_t)e * R * C;
    float* d = dst + (size_t)e * R * C;
    int c0 = blockIdx.x * 32, r0 = blockIdx.y * 32;
    for (int i = threadIdx.y; i < 32; i += 8)
        tile[i][threadIdx.x] = s[(size_t)(r0 + i) * C + c0 + threadIdx.x];
    __syncthreads();
    for (int i = threadIdx.y; i < 32; i += 8) {
        uint32_t v = f2tf32(tile[threadIdx.x][i]);
        *(uint32_t*)&d[(size_t)(c0 + i) * R + r0 + threadIdx.x] = v;
    }
}

// ---- tf32 GEMM with ldmatrix fragments: D[128,128] = A[gather, K] @ Bt[N, K]^T ----
template <int KFULL, int NFULL, bool GELU, bool GATHER>
__global__ __launch_bounds__(128, 2) void ffn_k(
    const float* __restrict__ A, const float* __restrict__ Bt,
    const float* __restrict__ bias,
    float* __restrict__ Out) {
    const int e  = blockIdx.z;
    const int ne = g_count[e];
    const int m0 = blockIdx.y * BM;
    if (m0 >= ne) return;
    const int n0   = blockIdx.x * BN;
    const int base = g_offset[e];

    extern __shared__ __align__(16) float smem[];
    const uint32_t sb = smem_u32(smem);
    const int tid  = threadIdx.x;
    const int lane = tid & 31;
    const int warp = tid >> 5;
    const int wm   = (warp & 1) * 64;
    const int wn   = (warp >> 1) * 64;

    // ---- cp.async addressing: 8 A-chunks + 8 B-chunks of 16B per thread ----
    const int crow = tid >> 3;      // 0..15
    const int cch  = tid & 7;       // k-chunk 0..7 (chunks of 4 floats cover BK=32)
    const float* srcA[8];
#pragma unroll
    for (int i = 0; i < 8; i++) {
        int row = crow + i * 16;
        int r;
        if (GATHER) r = g_tok[e * MAXB + min(m0 + row, ne - 1)];
        else        r = base + min(m0 + row, ne - 1);
        srcA[i] = A + (size_t)r * KFULL + cch * 4;
    }
    const float* srcB0 = Bt + (size_t)e * NFULL * KFULL + (size_t)(n0 + crow) * KFULL + cch * 4;
    const uint32_t dstw = (uint32_t)(crow * SROW + cch * 4) * 4u;  // byte offset of chunk

    auto load_stage = [&](int s, int k0) {
        uint32_t stA = sb + (uint32_t)(s * STAGE_BYTES);
        uint32_t stB = stA + A_BYTES;
#pragma unroll
        for (int i = 0; i < 8; i++)
            cp_async16(stA + dstw + i * (16 * SROW * 4), srcA[i] + k0);
#pragma unroll
        for (int i = 0; i < 8; i++)
            cp_async16(stB + dstw + i * (16 * SROW * 4), srcB0 + (size_t)i * 16 * KFULL + k0);
    };

    // ---- ldmatrix lane addressing (tf32-as-b16 trick) ----
    // A x4: matrices (m-lo,k-lo)(m-hi,k-lo)(m-lo,k-hi)(m-hi,k-hi)
    const int aRow = (lane & 7) + ((lane >> 3) & 1) * 8;
    const int aKl  = ((lane >> 4) & 1) * 4;
    // B x4: matrices (n-lo,k-lo)(n-lo,k-hi)(n-hi,k-lo)(n-hi,k-hi)
    const int bRow = (lane & 7) + ((lane >> 4) & 1) * 8;
    const int bKl  = ((lane >> 3) & 1) * 4;

    float acc[4][8][4];
#pragma unroll
    for (int i = 0; i < 4; i++)
#pragma unroll
        for (int j = 0; j < 8; j++)
#pragma unroll
            for (int k = 0; k < 4; k++) acc[i][j][k] = 0.f;

    constexpr int KITERS = KFULL / BK;
    load_stage(0, 0);
    cp_commit();
    load_stage(1, BK);
    cp_commit();

    for (int it = 0; it < KITERS; it++) {
        if (it + 1 == KITERS) cp_wait0(); else cp_wait1();
        __syncthreads();
        const int cs = it % NSTAGE;
        uint32_t stA = sb + (uint32_t)(cs * STAGE_BYTES);
        uint32_t stB = stA + A_BYTES;
#pragma unroll
        for (int ks = 0; ks < 4; ks++) {
            const int k0s = ks * 8;
            uint32_t af[4][4];
#pragma unroll
            for (int mt = 0; mt < 4; mt++) {
                uint32_t a = stA + (uint32_t)(((wm + mt * 16 + aRow) * SROW + k0s + aKl) * 4);
                ldsm4(af[mt][0], af[mt][1], af[mt][2], af[mt][3], a);
            }
            uint32_t bf[8][2];
#pragma unroll
            for (int p = 0; p < 4; p++) {
                uint32_t b = stB + (uint32_t)(((wn + p * 16 + bRow) * SROW + k0s + bKl) * 4);
                ldsm4(bf[2 * p][0], bf[2 * p][1], bf[2 * p + 1][0], bf[2 * p + 1][1], b);
            }
#pragma unroll
            for (int mt = 0; mt < 4; mt++)
#pragma unroll
                for (int nt = 0; nt < 8; nt++)
                    mma_tf32(acc[mt][nt], af[mt][0], af[mt][1], af[mt][2], af[mt][3],
                             bf[nt][0], bf[nt][1]);
        }
        if (it + 2 < KITERS) {
            load_stage((it + 2) % NSTAGE, (it + 2) * BK);
            cp_commit();
        }
    }

    // ---- epilogue ----
#pragma unroll
    for (int nt = 0; nt < 8; nt++) {
        int c = n0 + wn + nt * 8 + 2 * (lane & 3);
        float2 bb = *(const float2*)(bias + (size_t)e * NFULL + c);
#pragma unroll
        for (int mt = 0; mt < 4; mt++) {
            int r = wm + mt * 16 + (lane >> 2);
            int mrow0 = m0 + r, mrow1 = mrow0 + 8;
            if (mrow0 < ne) {
                float v0 = acc[mt][nt][0] + bb.x;
                float v1 = acc[mt][nt][1] + bb.y;
                if (GELU) {
                    v0 = v0 * normcdff(v0);
                    v1 = v1 * normcdff(v1);
                    uint2 o = { f2tf32(v0), f2tf32(v1) };
                    *(uint2*)(Out + (size_t)(base + mrow0) * NFULL + c) = o;
                } else {
                    float2 o = { v0, v1 };
                    *(float2*)(Out + (size_t)(base + mrow0) * NFULL + c) = o;
                }
            }
            if (mrow1 < ne) {
                float v2 = acc[mt][nt][2] + bb.x;
                float v3 = acc[mt][nt][3] + bb.y;
                if (GELU) {
                    v2 = v2 * normcdff(v2);
                    v3 = v3 * normcdff(v3);
                    uint2 o = { f2tf32(v2), f2tf32(v3) };
                    *(uint2*)(Out + (size_t)(base + mrow1) * NFULL + c) = o;
                } else {
                    float2 o = { v2, v3 };
                    *(float2*)(Out + (size_t)(base + mrow1) * NFULL + c) = o;
                }
            }
        }
    }
}

__global__ void combine_k(float* __restrict__ y) {
    int gid = blockIdx.x * blockDim.x + threadIdx.x;
    if (gid >= T_TOK * (DIM / 4)) return;
    int t = gid >> 7;
    int q = (gid & 127) * 4;
    int s0 = g_slot[t * 2 + 0], s1 = g_slot[t * 2 + 1];
    float w0 = g_slotw[t * 2 + 0], w1 = g_slotw[t * 2 + 1];
    int r0 = g_offset[s0 >> 13] + (s0 & (MAXB - 1));
    int r1 = g_offset[s1 >> 13] + (s1 & (MAXB - 1));
    float4 a = *(const float4*)(g_oscr + (size_t)r0 * DIM + q);
    float4 b = *(const float4*)(g_oscr + (size_t)r1 * DIM + q);
    float4 o;
    o.x = w0 * a.x + w1 * b.x;
    o.y = w0 * a.y + w1 * b.y;
    o.z = w0 * a.z + w1 * b.z;
    o.w = w0 * a.w + w1 * b.w;
    *(float4*)(y + (size_t)t * DIM + q) = o;
}

}  // namespace

extern "C" void kernel_launch(void* const* d_in, const int* in_sizes, int n_in,
                              void* d_out, int out_size) {
    const float* x  = (const float*)d_in[0];
    const float* gw = (const float*)d_in[1];
    const float* w1 = (const float*)d_in[2];
    const float* b1 = (const float*)d_in[3];
    const float* w2 = (const float*)d_in[4];
    const float* b2 = (const float*)d_in[5];
    float* y    = (float*)d_out;
    float* loss = y + (out_size - 1);

    static bool attr_done = false;
    if (!attr_done) {
        cudaFuncSetAttribute((const void*)ffn_k<DIM, FDIM, true, true>,
                             cudaFuncAttributeMaxDynamicSharedMemorySize, SMEM_BYTES);
        cudaFuncSetAttribute((const void*)ffn_k<FDIM, DIM, false, false>,
                             cudaFuncAttributeMaxDynamicSharedMemorySize, SMEM_BYTES);
        attr_done = true;
    }

    float *xr, *w1t, *w2t, *hid, *oscr;
    cudaGetSymbolAddress((void**)&xr,   g_xr);
    cudaGetSymbolAddress((void**)&w1t,  g_w1t);
    cudaGetSymbolAddress((void**)&w2t,  g_w2t);
    cudaGetSymbolAddress((void**)&hid,  g_hidden);
    cudaGetSymbolAddress((void**)&oscr, g_oscr);

    init_k<<<1, 32>>>();                                              // 1
    router_k<<<(T_TOK * 32 + 255) / 256, 256>>>(x, gw);               // 2
    finalize_k<<<1, 1>>>(loss);                                       // 3

    constexpr int XN4 = T_TOK * DIM / 4;
    round_k<<<(XN4 + 255) / 256, 256>>>(x, xr, XN4);                  // 4
    // w1 [E][D][F] -> [E][F][D]
    transpose_round_k<<<dim3(FDIM / 32, DIM / 32, NEXP), dim3(32, 8)>>>(w1, w1t, DIM, FDIM); // 5

    ffn_k<DIM, FDIM, true, true>                                      // 6 (ncu captures this)
        <<<dim3(FDIM / BN, MAXB / BM, NEXP), 128, SMEM_BYTES>>>(xr, w1t, b1, hid);

    // w2 [E][F][D] -> [E][D][F]
    transpose_round_k<<<dim3(DIM / 32, FDIM / 32, NEXP), dim3(32, 8)>>>(w2, w2t, FDIM, DIM); // 7

    ffn_k<FDIM, DIM, false, false>                                    // 8
        <<<dim3(DIM / BN, MAXB / BM, NEXP), 128, SMEM_BYTES>>>(hid, w2t, b2, oscr);

    combine_k<<<(T_TOK * (DIM / 4) + 255) / 256, 256>>>(y);           // 9
}

// round 7
// speedup vs baseline: 1.8495x; 1.7304x over previous
#include <cuda_runtime.h>
#include <cuda_fp16.h>
#include <math.h>
#include <stdint.h>

namespace {

constexpr int T_TOK = 8192;
constexpr int DIM   = 512;
constexpr int FDIM  = 2048;
constexpr int NEXP  = 8;
constexpr int MAXB  = 8192;
constexpr int NROWS = 2 * T_TOK;

// CTA 128x128, 8 warps as 2(M) x 4(N), warp tile 64x32, BK=32 (fp16), 3-stage
constexpr int BM = 128, BN = 128, BK = 32;
constexpr int AST = 40;                          // A smem row stride (halves)
constexpr int BST = 136;                         // B smem row stride (halves)
constexpr int A_PLANE = BM * AST * 2;            // 10240 B
constexpr int B_PLANE = BK * BST * 2;            // 8704 B
constexpr int STAGE   = A_PLANE + B_PLANE;       // 18944 B
constexpr int NSTAGE  = 3;
constexpr int SMEM_BYTES = NSTAGE * STAGE;       // 56832 B

// ---- device scratch ----
__device__ int   g_count[NEXP];
__device__ int   g_offset[NEXP];
__device__ float g_probsum[NEXP];
__device__ int   g_tok[NEXP * MAXB];
__device__ int   g_slot[T_TOK * 2];
__device__ float g_slotw[T_TOK * 2];
__device__ __half g_xh[(size_t)T_TOK * DIM];           // fp16 x
__device__ __half g_w1h[(size_t)NEXP * DIM * FDIM];    // fp16 w1, natural [E][K=D][N=F]
__device__ __half g_w2h[(size_t)NEXP * FDIM * DIM];    // fp16 w2, natural [E][K=F][N=D]
__device__ __half g_hid[(size_t)NROWS * FDIM];         // fp16 hidden
__device__ float  g_oscr[(size_t)NROWS * DIM];

// ---- PTX helpers ----
__device__ __forceinline__ uint32_t smem_u32(const void* p) {
    uint32_t a;
    asm("{ .reg .u64 t; cvta.to.shared.u64 t, %1; cvt.u32.u64 %0, t; }" : "=r"(a) : "l"(p));
    return a;
}
__device__ __forceinline__ void cp_async16(uint32_t saddr, const void* g) {
    asm volatile("cp.async.cg.shared.global [%0], [%1], 16;" :: "r"(saddr), "l"(g));
}
__device__ __forceinline__ void cp_commit() { asm volatile("cp.async.commit_group;" ::: "memory"); }
__device__ __forceinline__ void cp_wait1()  { asm volatile("cp.async.wait_group 1;" ::: "memory"); }
__device__ __forceinline__ void cp_wait0()  { asm volatile("cp.async.wait_group 0;" ::: "memory"); }

__device__ __forceinline__ void ldsm4(uint32_t& r0, uint32_t& r1, uint32_t& r2, uint32_t& r3,
                                      uint32_t a) {
    asm volatile("ldmatrix.sync.aligned.m8n8.x4.shared.b16 {%0,%1,%2,%3}, [%4];"
                 : "=r"(r0), "=r"(r1), "=r"(r2), "=r"(r3) : "r"(a));
}
__device__ __forceinline__ void ldsm4t(uint32_t& r0, uint32_t& r1, uint32_t& r2, uint32_t& r3,
                                       uint32_t a) {
    asm volatile("ldmatrix.sync.aligned.m8n8.x4.trans.shared.b16 {%0,%1,%2,%3}, [%4];"
                 : "=r"(r0), "=r"(r1), "=r"(r2), "=r"(r3) : "r"(a));
}
__device__ __forceinline__ void mma_f16(float c[4], const uint32_t a[4],
                                        uint32_t b0, uint32_t b1) {
    asm volatile(
        "mma.sync.aligned.m16n8k16.row.col.f32.f16.f16.f32 "
        "{%0,%1,%2,%3}, {%4,%5,%6,%7}, {%8,%9}, {%0,%1,%2,%3};"
        : "+f"(c[0]), "+f"(c[1]), "+f"(c[2]), "+f"(c[3])
        : "r"(a[0]), "r"(a[1]), "r"(a[2]), "r"(a[3]), "r"(b0), "r"(b1));
}

// ---- small kernels ----
__global__ void init_k() {
    if (threadIdx.x < NEXP) { g_count[threadIdx.x] = 0; g_probsum[threadIdx.x] = 0.f; }
}

__global__ void router_k(const float* __restrict__ x, const float* __restrict__ gw) {
    __shared__ float s_gw[DIM * NEXP];
    for (int i = threadIdx.x; i < DIM * NEXP; i += blockDim.x) s_gw[i] = gw[i];
    __syncthreads();

    int t    = (int)((blockIdx.x * blockDim.x + threadIdx.x) >> 5);
    int lane = threadIdx.x & 31;
    if (t >= T_TOK) return;

    const float* xr = x + (size_t)t * DIM;
    float acc[NEXP];
#pragma unroll
    for (int e = 0; e < NEXP; e++) acc[e] = 0.f;
    for (int d = lane; d < DIM; d += 32) {
        float xv = xr[d];
#pragma unroll
        for (int e = 0; e < NEXP; e++) acc[e] = fmaf(xv, s_gw[d * NEXP + e], acc[e]);
    }
#pragma unroll
    for (int off = 16; off; off >>= 1) {
#pragma unroll
        for (int e = 0; e < NEXP; e++)
            acc[e] += __shfl_xor_sync(0xffffffffu, acc[e], off);
    }
    if (lane != 0) return;

    float mx = acc[0];
#pragma unroll
    for (int e = 1; e < NEXP; e++) mx = fmaxf(mx, acc[e]);
    float p[NEXP]; float s = 0.f;
#pragma unroll
    for (int e = 0; e < NEXP; e++) { p[e] = expf(acc[e] - mx); s += p[e]; }
    float inv = 1.f / s;
#pragma unroll
    for (int e = 0; e < NEXP; e++) { p[e] *= inv; atomicAdd(&g_probsum[e], p[e]); }

    int i0 = 0;
#pragma unroll
    for (int e = 1; e < NEXP; e++) if (p[e] > p[i0]) i0 = e;
    int i1 = (i0 == 0) ? 1 : 0;
#pragma unroll
    for (int e = 0; e < NEXP; e++) if (e != i0 && p[e] > p[i1]) i1 = e;

    float w0 = p[i0], w1 = p[i1];
    float ws = 1.f / (w0 + w1);
    w0 *= ws; w1 *= ws;

    int p0 = atomicAdd(&g_count[i0], 1);
    g_tok[i0 * MAXB + p0] = t;
    g_slot[t * 2 + 0]  = i0 * MAXB + p0;
    g_slotw[t * 2 + 0] = w0;
    int p1 = atomicAdd(&g_count[i1], 1);
    g_tok[i1 * MAXB + p1] = t;
    g_slot[t * 2 + 1]  = i1 * MAXB + p1;
    g_slotw[t * 2 + 1] = w1;
}

__global__ void finalize_k(float* __restrict__ loss_out) {
    int off = 0;
    for (int e = 0; e < NEXP; e++) { g_offset[e] = off; off += g_count[e]; }
    float s = 0.f;
    for (int e = 0; e < NEXP; e++) {
        float m = g_probsum[e] * (1.f / (float)T_TOK);
        s += m * m;
    }
    *loss_out = (float)NEXP * s;
}

// fp32 -> fp16 elementwise
__global__ void h_conv_k(const float* __restrict__ src, __half* __restrict__ dst, int n4) {
    int i = blockIdx.x * blockDim.x + threadIdx.x;
    if (i >= n4) return;
    float4 v = ((const float4*)src)[i];
    ((__half2*)dst)[2 * i]     = __floats2half2_rn(v.x, v.y);
    ((__half2*)dst)[2 * i + 1] = __floats2half2_rn(v.z, v.w);
}

// ---- fp16 tensor-core FFN GEMM: D[128,128] = A[gather, K] @ B[K, N] ----
template <int KFULL, int NFULL, bool GELU, bool GATHER>
__global__ __launch_bounds__(256, 2) void ffn_k(
    const __half* __restrict__ A, const __half* __restrict__ B,
    const float* __restrict__ bias,
    __half* __restrict__ OutH, float* __restrict__ OutF) {
    const int e  = blockIdx.z;
    const int ne = g_count[e];
    const int m0 = blockIdx.y * BM;
    if (m0 >= ne) return;
    const int n0   = blockIdx.x * BN;
    const int base = g_offset[e];

    extern __shared__ __align__(16) char smem[];
    const uint32_t sb = smem_u32(smem);
    const int tid  = threadIdx.x;
    const int lane = tid & 31;
    const int warp = tid >> 5;
    const int wm   = (warp & 1) * 64;
    const int wn   = (warp >> 1) * 32;

    // ---- cp.async addressing: 2 A-chunks + 2 B-chunks of 16B per thread ----
    const __half* sA[2];
    uint32_t dA[2];
#pragma unroll
    for (int l = 0; l < 2; l++) {
        int idx = tid + l * 256;          // 0..511
        int row = idx >> 2;               // 0..127
        int ch  = idx & 3;                // 4 x 16B chunks cover 32 halves
        int r;
        if (GATHER) r = g_tok[e * MAXB + min(m0 + row, ne - 1)];
        else        r = base + min(m0 + row, ne - 1);
        sA[l] = A + (size_t)r * KFULL + ch * 8;
        dA[l] = (uint32_t)(row * (AST * 2) + ch * 16);
    }
    const __half* sB[2];
    uint32_t dB[2];
    const __half* Bp = B + (size_t)e * KFULL * NFULL;
#pragma unroll
    for (int l = 0; l < 2; l++) {
        int idx = tid + l * 256;
        int k  = idx >> 4;                // 0..31
        int ch = idx & 15;                // 16 chunks of 8 halves across N=128
        sB[l] = Bp + (size_t)k * NFULL + n0 + ch * 8;
        dB[l] = (uint32_t)(A_PLANE + k * (BST * 2) + ch * 16);
    }

    auto load_stage = [&](int s, int k0) {
        uint32_t st = sb + (uint32_t)(s * STAGE);
#pragma unroll
        for (int l = 0; l < 2; l++) cp_async16(st + dA[l], sA[l] + k0);
#pragma unroll
        for (int l = 0; l < 2; l++) cp_async16(st + dB[l], sB[l] + (size_t)k0 * NFULL);
    };

    // ---- ldmatrix lane addressing (identical to round-5 proven layout) ----
    const int lm = lane >> 3;
    const int aR = (lm & 1) * 8 + (lane & 7);
    const int aK = (lm >> 1) * 8;
    const int bK = (lm & 1) * 8 + (lane & 7);
    const int bN = (lm >> 1) * 8;

    float acc[4][4][4];
#pragma unroll
    for (int i = 0; i < 4; i++)
#pragma unroll
        for (int j = 0; j < 4; j++)
#pragma unroll
            for (int k = 0; k < 4; k++) acc[i][j][k] = 0.f;

    constexpr int KITERS = KFULL / BK;
    load_stage(0, 0);
    cp_commit();
    load_stage(1, BK);
    cp_commit();

    for (int it = 0; it < KITERS; it++) {
        if (it + 1 == KITERS) cp_wait0(); else cp_wait1();
        __syncthreads();
        uint32_t st = sb + (uint32_t)((it % NSTAGE) * STAGE);
#pragma unroll
        for (int ks = 0; ks < 2; ks++) {
            const int k0s = ks * 16;
            uint32_t ah[4][4];
#pragma unroll
            for (int mt = 0; mt < 4; mt++) {
                uint32_t a0 = st + (uint32_t)(((wm + mt * 16 + aR) * AST + k0s + aK) * 2);
                ldsm4(ah[mt][0], ah[mt][1], ah[mt][2], ah[mt][3], a0);
            }
#pragma unroll
            for (int pair = 0; pair < 2; pair++) {
                uint32_t b0 = st + A_PLANE +
                              (uint32_t)(((k0s + bK) * BST + wn + pair * 16 + bN) * 2);
                uint32_t bh[4];
                ldsm4t(bh[0], bh[1], bh[2], bh[3], b0);
#pragma unroll
                for (int j = 0; j < 2; j++) {
                    const int nt = pair * 2 + j;
#pragma unroll
                    for (int mt = 0; mt < 4; mt++)
                        mma_f16(acc[mt][nt], ah[mt], bh[2 * j], bh[2 * j + 1]);
                }
            }
        }
        if (it + 2 < KITERS) {
            load_stage((it + 2) % NSTAGE, (it + 2) * BK);
            cp_commit();
        }
    }

    // ---- epilogue ----
#pragma unroll
    for (int nt = 0; nt < 4; nt++) {
        int c = n0 + wn + nt * 8 + 2 * (lane & 3);
        float2 bb = *(const float2*)(bias + (size_t)e * NFULL + c);
#pragma unroll
        for (int mt = 0; mt < 4; mt++) {
            int r = wm + mt * 16 + (lane >> 2);
            int mrow0 = m0 + r, mrow1 = mrow0 + 8;
            if (GELU) {
                if (mrow0 < ne) {
                    float v0 = acc[mt][nt][0] + bb.x;
                    float v1 = acc[mt][nt][1] + bb.y;
                    v0 = v0 * normcdff(v0);
                    v1 = v1 * normcdff(v1);
                    *(__half2*)(OutH + (size_t)(base + mrow0) * NFULL + c) =
                        __floats2half2_rn(v0, v1);
                }
                if (mrow1 < ne) {
                    float v2 = acc[mt][nt][2] + bb.x;
                    float v3 = acc[mt][nt][3] + bb.y;
                    v2 = v2 * normcdff(v2);
                    v3 = v3 * normcdff(v3);
                    *(__half2*)(OutH + (size_t)(base + mrow1) * NFULL + c) =
                        __floats2half2_rn(v2, v3);
                }
            } else {
                if (mrow0 < ne) {
                    float2 o = { acc[mt][nt][0] + bb.x, acc[mt][nt][1] + bb.y };
                    *(float2*)(OutF + (size_t)(base + mrow0) * NFULL + c) = o;
                }
                if (mrow1 < ne) {
                    float2 o = { acc[mt][nt][2] + bb.x, acc[mt][nt][3] + bb.y };
                    *(float2*)(OutF + (size_t)(base + mrow1) * NFULL + c) = o;
                }
            }
        }
    }
}

__global__ void combine_k(float* __restrict__ y) {
    int gid = blockIdx.x * blockDim.x + threadIdx.x;
    if (gid >= T_TOK * (DIM / 4)) return;
    int t = gid >> 7;
    int q = (gid & 127) * 4;
    int s0 = g_slot[t * 2 + 0], s1 = g_slot[t * 2 + 1];
    float w0 = g_slotw[t * 2 + 0], w1 = g_slotw[t * 2 + 1];
    int r0 = g_offset[s0 >> 13] + (s0 & (MAXB - 1));
    int r1 = g_offset[s1 >> 13] + (s1 & (MAXB - 1));
    float4 a = *(const float4*)(g_oscr + (size_t)r0 * DIM + q);
    float4 b = *(const float4*)(g_oscr + (size_t)r1 * DIM + q);
    float4 o;
    o.x = w0 * a.x + w1 * b.x;
    o.y = w0 * a.y + w1 * b.y;
    o.z = w0 * a.z + w1 * b.z;
    o.w = w0 * a.w + w1 * b.w;
    *(float4*)(y + (size_t)t * DIM + q) = o;
}

}  // namespace

extern "C" void kernel_launch(void* const* d_in, const int* in_sizes, int n_in,
                              void* d_out, int out_size) {
    const float* x  = (const float*)d_in[0];
    const float* gw = (const float*)d_in[1];
    const float* w1 = (const float*)d_in[2];
    const float* b1 = (const float*)d_in[3];
    const float* w2 = (const float*)d_in[4];
    const float* b2 = (const float*)d_in[5];
    float* y    = (float*)d_out;
    float* loss = y + (out_size - 1);

    static bool attr_done = false;
    if (!attr_done) {
        cudaFuncSetAttribute((const void*)ffn_k<DIM, FDIM, true, true>,
                             cudaFuncAttributeMaxDynamicSharedMemorySize, SMEM_BYTES);
        cudaFuncSetAttribute((const void*)ffn_k<FDIM, DIM, false, false>,
                             cudaFuncAttributeMaxDynamicSharedMemorySize, SMEM_BYTES);
        attr_done = true;
    }

    __half *xh, *w1h, *w2h, *hid;
    float* oscr;
    cudaGetSymbolAddress((void**)&xh,   g_xh);
    cudaGetSymbolAddress((void**)&w1h,  g_w1h);
    cudaGetSymbolAddress((void**)&w2h,  g_w2h);
    cudaGetSymbolAddress((void**)&hid,  g_hid);
    cudaGetSymbolAddress((void**)&oscr, g_oscr);

    init_k<<<1, 32>>>();                                              // 1
    router_k<<<(T_TOK * 32 + 255) / 256, 256>>>(x, gw);               // 2
    finalize_k<<<1, 1>>>(loss);                                       // 3

    constexpr int XN4  = T_TOK * DIM / 4;
    constexpr int W1N4 = NEXP * DIM * FDIM / 4;
    constexpr int W2N4 = NEXP * FDIM * DIM / 4;
    h_conv_k<<<(XN4 + 255) / 256, 256>>>(x, xh, XN4);                 // 4
    h_conv_k<<<(W1N4 + 255) / 256, 256>>>(w1, w1h, W1N4);             // 5

    ffn_k<DIM, FDIM, true, true>                                      // 6 (ncu captures this)
        <<<dim3(FDIM / BN, MAXB / BM, NEXP), 256, SMEM_BYTES>>>(xh, w1h, b1, hid, nullptr);

    h_conv_k<<<(W2N4 + 255) / 256, 256>>>(w2, w2h, W2N4);             // 7

    ffn_k<FDIM, DIM, false, false>                                    // 8
        <<<dim3(DIM / BN, MAXB / BM, NEXP), 256, SMEM_BYTES>>>(hid, w2h, b2, nullptr, oscr);

    combine_k<<<(T_TOK * (DIM / 4) + 255) / 256, 256>>>(y);           // 9
}